// round 6
// baseline (speedup 1.0000x reference)
#include <cuda_runtime.h>
#include <cuda_fp16.h>
#include <cuda_bf16.h>

// Problem constants (from reference_code)
#define N_PATHS  10000000
#define MAX_LEN  3
#define N_NODES  100000
#define HIDDEN   128

// Nodes resident in shared memory (fp16, planar): 3 * 19000 * 2 = 114000 B.
// 2 CTAs/SM x 114000 B = 228000 B <= SM smem budget -> 64 warps/SM.
#define NS         19000
#define SMEM_BYTES (3 * NS * 2)

// fp16 planar projection table: g_t16[l * N_NODES + node]
__device__ __half g_t16[3 * N_NODES];

// ---------------------------------------------------------------------------
// Kernel 1: proj[l][node] = dot(feature[node], W[l][0]) -> fp16 planar table.
// One warp per node; lane t covers dims [4t,4t+4) via float4.
// ---------------------------------------------------------------------------
__global__ void proj_kernel(const float* __restrict__ nf,
                            const float* __restrict__ W) {
    const int lane   = threadIdx.x & 31;
    const int warpIn = threadIdx.x >> 5;
    const int node   = blockIdx.x * (blockDim.x >> 5) + warpIn;
    if (node >= N_NODES) return;

    const float4 w0 = __ldg(((const float4*)W) + 0  + lane);
    const float4 w1 = __ldg(((const float4*)W) + 32 + lane);
    const float4 w2 = __ldg(((const float4*)W) + 64 + lane);

    const float4 f = __ldg(((const float4*)nf) + (size_t)node * 32 + lane);

    float s0 = f.x * w0.x + f.y * w0.y + f.z * w0.z + f.w * w0.w;
    float s1 = f.x * w1.x + f.y * w1.y + f.z * w1.z + f.w * w1.w;
    float s2 = f.x * w2.x + f.y * w2.y + f.z * w2.z + f.w * w2.w;

    #pragma unroll
    for (int o = 16; o > 0; o >>= 1) {
        s0 += __shfl_xor_sync(0xFFFFFFFFu, s0, o);
        s1 += __shfl_xor_sync(0xFFFFFFFFu, s1, o);
        s2 += __shfl_xor_sync(0xFFFFFFFFu, s2, o);
    }

    if (lane == 0) {
        g_t16[0 * N_NODES + node] = __float2half(s0);
        g_t16[1 * N_NODES + node] = __float2half(s1);
        g_t16[2 * N_NODES + node] = __float2half(s2);
    }
}

// ---------------------------------------------------------------------------
// Kernel 2: hybrid gather + masked mean, R2 code shape, full occupancy.
//   p in [0, NS)      -> clamped LDS from 114 KB fp16 smem table
//   p in [NS, NODES)  -> guarded LDG (predicated) from fp16 global table
//   p < 0             -> contributes 0
// 4 paths (12 accesses) per thread per iteration.
// ---------------------------------------------------------------------------
__global__ void __launch_bounds__(1024, 2)
gather_kernel(const int* __restrict__ paths, float* __restrict__ out) {
    extern __shared__ __half s_tab[];  // [3][NS]

    const int tid = threadIdx.x;

    // Cooperative smem fill: 114000 B = 7125 x 16 B
    {
        const float4* src = (const float4*)g_t16;  // first 3*NS halves... NO:
        // planar copy per plane so smem plane l matches g_t16 plane l prefix
    }
    #pragma unroll
    for (int l = 0; l < 3; l++) {
        const float4* src = (const float4*)(g_t16 + l * N_NODES);
        float4*       dst = (float4*)(s_tab + l * NS);
        for (int i = tid; i < (NS * 2) / 16; i += 1024)
            dst[i] = __ldg(src + i);
    }
    __syncthreads();

    const long long QT = N_PATHS / 4;  // 2.5M quads
    const long long q0 = (long long)blockIdx.x * QT / gridDim.x;
    const long long q1 = (long long)(blockIdx.x + 1) * QT / gridDim.x;

    for (long long q = q0 + tid; q < q1; q += 1024) {
        const int4* p4 = ((const int4*)paths) + q * 3;
        int4 v0 = __ldg(p4 + 0);
        int4 v1 = __ldg(p4 + 1);
        int4 v2 = __ldg(p4 + 2);

        int idx[12] = { v0.x, v0.y, v0.z, v0.w,
                        v1.x, v1.y, v1.z, v1.w,
                        v2.x, v2.y, v2.z, v2.w };

        float4 res;
        float* r = (float*)&res;

        #pragma unroll
        for (int k = 0; k < 4; k++) {
            float s = 0.0f;
            int   cnt = 0;
            #pragma unroll
            for (int l = 0; l < 3; l++) {
                const int p = idx[k * 3 + l];

                // guarded global load (predicated LDG, no branch)
                float vg = 0.0f;
                if (p >= NS)
                    vg = __half2float(__ldg(g_t16 + l * N_NODES + p));

                // unconditional clamped smem load (cheap crossbar gather)
                unsigned int ps = ((unsigned int)p < NS) ? (unsigned int)p : 0u;
                float vs = __half2float(s_tab[l * NS + ps]);

                // select: global / smem / zero
                float v = (p >= NS) ? vg
                        : (((unsigned int)p < NS) ? vs : 0.0f);
                s   += v;
                cnt += (p >= 0);
            }
            float inv = (cnt == 3) ? (1.0f / 3.0f)
                                   : ((cnt == 2) ? 0.5f : 1.0f);
            r[k] = s * inv;
        }

        ((float4*)out)[q] = res;
    }
}

// ---------------------------------------------------------------------------
// Launch. Inputs identified by element count:
//   30,000,000 -> paths (int32 [10M,3]); 12,800,000 -> node_feature; 384 -> W
// ---------------------------------------------------------------------------
extern "C" void kernel_launch(void* const* d_in, const int* in_sizes, int n_in,
                              void* d_out, int out_size) {
    const void*  paths_raw = nullptr;
    const float* nf        = nullptr;
    const float* W         = nullptr;

    for (int i = 0; i < n_in; i++) {
        if      (in_sizes[i] == N_PATHS * MAX_LEN)  paths_raw = d_in[i];
        else if (in_sizes[i] == N_NODES * HIDDEN)   nf        = (const float*)d_in[i];
        else if (in_sizes[i] == MAX_LEN * HIDDEN)   W         = (const float*)d_in[i];
    }

    float* out = (float*)d_out;

    static bool attr_done = false;
    if (!attr_done) {
        cudaFuncSetAttribute(gather_kernel,
                             cudaFuncAttributeMaxDynamicSharedMemorySize,
                             SMEM_BYTES);
        cudaFuncSetAttribute(gather_kernel,
                             cudaFuncAttributePreferredSharedMemoryCarveout,
                             100);  // max smem carveout so 2 CTAs co-reside
        attr_done = true;
    }

    // proj: one warp per node
    {
        const int threads = 256;
        const int warpsPerBlock = threads / 32;
        const int blocks = (N_NODES + warpsPerBlock - 1) / warpsPerBlock;
        proj_kernel<<<blocks, threads>>>(nf, W);
    }

    // gather: 2 CTAs per SM (296 total), 1024 threads, 114 KB smem each
    gather_kernel<<<296, 1024, SMEM_BYTES>>>((const int*)paths_raw, out);
}

// round 7
// speedup vs baseline: 1.8511x; 1.8511x over previous
#include <cuda_runtime.h>
#include <cuda_fp16.h>
#include <cuda_bf16.h>

// Problem constants (from reference_code)
#define N_PATHS  10000000
#define MAX_LEN  3
#define N_NODES  100000
#define HIDDEN   128

// fp16 planar projection table: g_t16[l * N_NODES + node], 600 KB total.
// Halved footprint vs fp32 -> ~2x L1 hit rate, ~0.5x L2 sector traffic.
__device__ __half g_t16[3 * N_NODES];

// ---------------------------------------------------------------------------
// Kernel 1: proj[l][node] = dot(feature[node], W[l][0]) -> fp16 planar table.
// One warp per node; lane t covers dims [4t,4t+4) via float4.
// ---------------------------------------------------------------------------
__global__ void proj_kernel(const float* __restrict__ nf,
                            const float* __restrict__ W) {
    const int lane   = threadIdx.x & 31;
    const int warpIn = threadIdx.x >> 5;
    const int node   = blockIdx.x * (blockDim.x >> 5) + warpIn;
    if (node >= N_NODES) return;

    const float4 w0 = __ldg(((const float4*)W) + 0  + lane);
    const float4 w1 = __ldg(((const float4*)W) + 32 + lane);
    const float4 w2 = __ldg(((const float4*)W) + 64 + lane);

    const float4 f = __ldg(((const float4*)nf) + (size_t)node * 32 + lane);

    float s0 = f.x * w0.x + f.y * w0.y + f.z * w0.z + f.w * w0.w;
    float s1 = f.x * w1.x + f.y * w1.y + f.z * w1.z + f.w * w1.w;
    float s2 = f.x * w2.x + f.y * w2.y + f.z * w2.z + f.w * w2.w;

    #pragma unroll
    for (int o = 16; o > 0; o >>= 1) {
        s0 += __shfl_xor_sync(0xFFFFFFFFu, s0, o);
        s1 += __shfl_xor_sync(0xFFFFFFFFu, s1, o);
        s2 += __shfl_xor_sync(0xFFFFFFFFu, s2, o);
    }

    if (lane == 0) {
        g_t16[0 * N_NODES + node] = __float2half(s0);
        g_t16[1 * N_NODES + node] = __float2half(s1);
        g_t16[2 * N_NODES + node] = __float2half(s2);
    }
}

// ---------------------------------------------------------------------------
// Kernel 2: gather + masked mean. Exact R2 code shape (the measured-best):
// 4 paths/thread, 12 predicated table gathers, 256-thread blocks.
// Streaming data (paths in, scores out) uses evict-first (.cs) so the fp16
// table keeps L1 residency; table gathers use default caching LDG.
// ---------------------------------------------------------------------------
__global__ void __launch_bounds__(256)
gather_kernel(const int* __restrict__ paths, float* __restrict__ out) {
    const long long tid = (long long)blockIdx.x * blockDim.x + threadIdx.x;
    if (tid >= (N_PATHS / 4)) return;

    // 4 paths = 12 int32 = 3 x int4, evict-first streaming loads
    const int4* p4 = ((const int4*)paths) + tid * 3;
    int4 v0 = __ldcs(p4 + 0);
    int4 v1 = __ldcs(p4 + 1);
    int4 v2 = __ldcs(p4 + 2);

    int idx[12] = { v0.x, v0.y, v0.z, v0.w,
                    v1.x, v1.y, v1.z, v1.w,
                    v2.x, v2.y, v2.z, v2.w };

    float4 res;
    float* r = (float*)&res;

    #pragma unroll
    for (int k = 0; k < 4; k++) {
        float s = 0.0f;
        int   cnt = 0;
        #pragma unroll
        for (int l = 0; l < 3; l++) {
            const int p = idx[k * 3 + l];
            if (p >= 0) {                     // predicated LDG + SEL (no branch)
                s += __half2float(g_t16[l * N_NODES + p]);
                cnt++;
            }
        }
        float inv = (cnt == 3) ? (1.0f / 3.0f)
                               : ((cnt == 2) ? 0.5f : 1.0f);
        r[k] = s * inv;
    }

    __stcs(((float4*)out) + tid, res);        // evict-first streaming store
}

// ---------------------------------------------------------------------------
// Launch. Inputs identified by element count:
//   30,000,000 -> paths (int32 [10M,3]); 12,800,000 -> node_feature; 384 -> W
// ---------------------------------------------------------------------------
extern "C" void kernel_launch(void* const* d_in, const int* in_sizes, int n_in,
                              void* d_out, int out_size) {
    const void*  paths_raw = nullptr;
    const float* nf        = nullptr;
    const float* W         = nullptr;

    for (int i = 0; i < n_in; i++) {
        if      (in_sizes[i] == N_PATHS * MAX_LEN)  paths_raw = d_in[i];
        else if (in_sizes[i] == N_NODES * HIDDEN)   nf        = (const float*)d_in[i];
        else if (in_sizes[i] == MAX_LEN * HIDDEN)   W         = (const float*)d_in[i];
    }

    float* out = (float*)d_out;

    // proj: one warp per node
    {
        const int threads = 256;
        const int warpsPerBlock = threads / 32;
        const int blocks = (N_NODES + warpsPerBlock - 1) / warpsPerBlock;
        proj_kernel<<<blocks, threads>>>(nf, W);
    }

    // gather: 2.5M threads, 4 paths each (R2-proven launch shape)
    {
        const int threads = 256;
        const long long nThreads = N_PATHS / 4;
        const int blocks = (int)((nThreads + threads - 1) / threads);
        gather_kernel<<<blocks, threads>>>((const int*)paths_raw, out);
    }
}